// round 16
// baseline (speedup 1.0000x reference)
#include <cuda_runtime.h>
#include <cuda_fp16.h>
#include <math.h>
#include <stdint.h>

#define T_TOK 2048
#define HDIM  1024
#define NE    16
#define TOPK  4
#define NG    4
#define TGSEL 2
#define IMOE  512
#define RSCALE 2.5f

typedef __half fp16;

// ======================= device scratch ========================================
__device__ int   g_tidx[T_TOK * TOPK];
__device__ float g_tw  [T_TOK * TOPK];
__device__ int   g_cur [NE];
__device__ int   g_off [NE + 1];
__device__ int   g_ptok[T_TOK * TOPK];
__device__ int   g_pos [T_TOK * TOPK];
__device__ float g_pw  [T_TOK * TOPK];

__device__ fp16  g_yh [(size_t)T_TOK * TOPK * 1024];   // routed down out (weighted, fp16)
__device__ float g_ysh[(size_t)T_TOK * 1024];           // shared down out (fp32)

// fp16 operands
__device__ fp16 g_xh [T_TOK * HDIM];
__device__ fp16 g_hh [T_TOK * TOPK * IMOE];
__device__ fp16 g_hsh[T_TOK * 1024];
__device__ fp16 g_gwh[NE * IMOE * HDIM];
__device__ fp16 g_uwh[NE * IMOE * HDIM];
__device__ fp16 g_dwh[NE * HDIM * IMOE];
__device__ fp16 g_sgh[HDIM * 1024];
__device__ fp16 g_suh[HDIM * 1024];
__device__ fp16 g_sdh[HDIM * 1024];

// ======================= fused prep: convert + router ==========================
#define NSEG 7
#define CVT_TOTAL 7602176            // total float4 units across all 7 segments
#define CVT_BLKS  (CVT_TOTAL / 512)  // 14848 (exact)

struct CvtArgs {
    const float4* src[NSEG];
    uint2*        dst[NSEG];
    int           cum[NSEG];
};

__global__ void __launch_bounds__(512)
prep_kernel(CvtArgs a,
            const float* __restrict__ x,
            const float* __restrict__ rw,
            const float* __restrict__ ebias) {
    if (blockIdx.x < CVT_BLKS) {
        int i = blockIdx.x * 512 + threadIdx.x;
        if (i < CVT_TOTAL) {
            int s = 0;
            #pragma unroll
            for (int k = 1; k < NSEG; k++) if (i >= a.cum[k]) s = k;
            int off = i - a.cum[s];
            float4 v = a.src[s][off];
            __half2 p0 = __floats2half2_rn(v.x, v.y);
            __half2 p1 = __floats2half2_rn(v.z, v.w);
            a.dst[s][off] = make_uint2(*(uint32_t*)&p0, *(uint32_t*)&p1);
        }
        return;
    }

    int t    = blockIdx.x - CVT_BLKS;
    int w    = threadIdx.x >> 5;
    int lane = threadIdx.x & 31;

    const float* xr = x  + (size_t)t * HDIM;
    const float* wr = rw + (size_t)w * HDIM;
    float s = 0.f;
    for (int k = lane; k < HDIM; k += 32) s += xr[k] * wr[k];
    #pragma unroll
    for (int o = 16; o; o >>= 1) s += __shfl_xor_sync(0xffffffffu, s, o);

    __shared__ float sdot[NE];
    if (lane == 0) sdot[w] = s;
    __syncthreads();

    if (threadIdx.x == 0) {
        float sraw[NE], sc[NE];
        #pragma unroll
        for (int e = 0; e < NE; e++) {
            sraw[e] = 1.f / (1.f + expf(-sdot[e]));
            sc[e]   = sraw[e] + ebias[e];
        }
        float gsc[NG];
        #pragma unroll
        for (int g = 0; g < NG; g++) {
            float m1 = -1e30f, m2 = -1e30f;
            #pragma unroll
            for (int j = 0; j < NE / NG; j++) {
                float v = sc[g * (NE / NG) + j];
                if (v > m1) { m2 = m1; m1 = v; }
                else if (v > m2) { m2 = v; }
            }
            gsc[g] = m1 + m2;
        }
        bool gsel[NG] = {false, false, false, false};
        for (int r = 0; r < TGSEL; r++) {
            int best = -1; float bv = -1e30f;
            for (int g = 0; g < NG; g++)
                if (!gsel[g] && gsc[g] > bv) { bv = gsc[g]; best = g; }
            gsel[best] = true;
        }
        float masked[NE];
        #pragma unroll
        for (int e = 0; e < NE; e++)
            masked[e] = gsel[e / (NE / NG)] ? sc[e] : 0.0f;
        int idx[TOPK]; float tw[TOPK]; float wsum = 0.f;
        for (int r = 0; r < TOPK; r++) {
            int best = 0; float bv = -1e30f;
            for (int e = 0; e < NE; e++)
                if (masked[e] > bv) { bv = masked[e]; best = e; }
            idx[r] = best; tw[r] = sraw[best];
            masked[best] = -1e30f;
            wsum += tw[r];
        }
        float inv = RSCALE / (wsum + 1e-20f);
        for (int r = 0; r < TOPK; r++) {
            g_tidx[t * TOPK + r] = idx[r];
            g_tw  [t * TOPK + r] = tw[r] * inv;
        }
    }
}

// ======================= scan (histogram + prefix) =============================
__global__ void __launch_bounds__(512)
scan_kernel() {
    __shared__ int cnt[NE];
    int tid = threadIdx.x;
    if (tid < NE) cnt[tid] = 0;
    __syncthreads();
    for (int i = tid; i < T_TOK * TOPK; i += 512)
        atomicAdd(&cnt[g_tidx[i]], 1);
    __syncthreads();
    if (tid == 0) {
        int acc = 0;
        for (int e = 0; e < NE; e++) { g_off[e] = acc; acc += cnt[e]; }
        g_off[NE] = acc;
    }
    if (tid < NE) g_cur[tid] = 0;
}

__global__ void scatter_kernel() {
    int s = blockIdx.x * blockDim.x + threadIdx.x;
    if (s >= T_TOK * TOPK) return;
    int e   = g_tidx[s];
    int pos = g_off[e] + atomicAdd(&g_cur[e], 1);
    g_ptok[pos] = s >> 2;
    g_pw  [pos] = g_tw[s];
    g_pos [s]   = pos;
}

// ======================= shared GEMM machinery =================================
// k-chunk = 64 elems (128B/row + 16B pad = 144B rows). A rows 0..127, B rows
// 128..255 within a stage. 3 stages, prefetch issued before compute.
#define ROWB   144
#define AH_OFF 0
#define BH_OFF 18432
#define STG_B  36864
#define NSTG   3
#define SMEM_DYN (NSTG * STG_B)
#define EP_LD  132

static __device__ __forceinline__ uint32_t smem_u32(const void* p) {
    uint32_t a;
    asm("{ .reg .u64 t; cvta.to.shared.u64 t, %1; cvt.u32.u64 %0, t; }"
        : "=r"(a) : "l"(p));
    return a;
}

#define LDSM_X4(r0, r1, r2, r3, addr) \
    asm volatile("ldmatrix.sync.aligned.m8n8.x4.shared.b16 {%0,%1,%2,%3}, [%4];" \
        : "=r"(r0), "=r"(r1), "=r"(r2), "=r"(r3) : "r"(addr))

#define MMA16816F16(d, a, b) \
    asm volatile("mma.sync.aligned.m16n8k16.row.col.f32.f16.f16.f32 " \
        "{%0,%1,%2,%3},{%4,%5,%6,%7},{%8,%9},{%0,%1,%2,%3};" \
        : "+f"((d)[0]), "+f"((d)[1]), "+f"((d)[2]), "+f"((d)[3]) \
        : "r"((a)[0]), "r"((a)[1]), "r"((a)[2]), "r"((a)[3]), \
          "r"((b)[0]), "r"((b)[1]))

#define CP16(dst, src, sz) \
    asm volatile("cp.async.cg.shared.global [%0], [%1], 16, %2;" \
        :: "r"(dst), "l"(src), "r"(sz) : "memory")
#define CP_COMMIT() asm volatile("cp.async.commit_group;" ::: "memory")
#define CP_WAIT1()  asm volatile("cp.async.wait_group 1;" ::: "memory")
#define CP_WAIT0()  asm volatile("cp.async.wait_group 0;" ::: "memory")

// ======================= gateup_all: routed (z<NE) + shared (z==NE) ============
__global__ void __launch_bounds__(256, 2)
gateup_all_kernel(const fp16* __restrict__ xh,
                  const fp16* __restrict__ gwh, const fp16* __restrict__ uwh,
                  const fp16* __restrict__ sgh, const fp16* __restrict__ suh,
                  fp16* __restrict__ hh, fp16* __restrict__ hsh)
{
    int z = blockIdx.z;
    bool se = (z == NE);
    int rbeg, rend, nxb, ldh;
    const fp16 *Bg, *Bu;
    fp16* Hout;
    if (se) {
        rbeg = 0; rend = T_TOK; nxb = 16; ldh = 1024;
        Bg = sgh; Bu = suh; Hout = hsh;
    } else {
        rbeg = g_off[z]; rend = g_off[z + 1]; nxb = 8; ldh = 512;
        Bg = gwh + (size_t)z * IMOE * HDIM;
        Bu = uwh + (size_t)z * IMOE * HDIM;
        Hout = hh;
    }
    if (blockIdx.x >= nxb) return;
    int row0 = rbeg + blockIdx.y * 128;
    if (row0 >= rend) return;
    int n0h = blockIdx.x * 64;
    const int KD = 1024;

    extern __shared__ __align__(16) char dynsmem[];
    uint32_t sbase = smem_u32(dynsmem);

    int tid  = threadIdx.x;
    int lane = tid & 31, wid = tid >> 5;
    int wm = (wid >> 2) * 64;
    int wn = (wid & 3) * 32;

    // staging: thread -> (row = tid>>1, 32-elem half = tid&1), 4x16B cp.async each
    int srow = tid >> 1;
    int kh32 = (tid & 1) << 5;                 // element offset 0 / 32
    int  arow_s = row0 + srow;
    bool avalid = (arow_s < rend);
    const fp16* pAh = xh;
    if (avalid) {
        int tokr = se ? arow_s : g_ptok[arow_s];
        pAh = xh + (size_t)tokr * HDIM + kh32;
    }
    const fp16* pBh = (srow < 64)
        ? Bg + (size_t)(n0h + srow) * KD + kh32
        : Bu + (size_t)(n0h + srow - 64) * KD + kh32;
    uint32_t st_off = (uint32_t)(srow * ROWB + (tid & 1) * 64);
    uint32_t asz = avalid ? 16u : 0u;

    int a_r  = wm + (lane & 7) + ((lane >> 3) & 1) * 8;
    int a_k  = ((lane >> 4) & 1) * 8;
    uint32_t a_lm = (uint32_t)(a_r * ROWB + a_k * 2);
    int b_r  = wn + (lane & 7) + ((lane >> 4) & 1) * 8;
    int b_k  = ((lane >> 3) & 1) * 8;
    uint32_t b_lm = (uint32_t)(b_r * ROWB + b_k * 2);

    float acc[4][4][4];
    #pragma unroll
    for (int i = 0; i < 4; i++)
        #pragma unroll
        for (int j = 0; j < 4; j++)
            #pragma unroll
            for (int q = 0; q < 4; q++) acc[i][j][q] = 0.f;

    const int nchunk = KD >> 6;   // 16

    auto issue = [&](int ch) {
        if (ch < nchunk) {
            uint32_t sb = sbase + (uint32_t)(ch % NSTG) * STG_B;
            int k0 = ch << 6;
            const fp16* sa_h = pAh + k0;
            const fp16* sb_h = pBh + k0;
            CP16(sb + AH_OFF + st_off,      sa_h,      asz);
            CP16(sb + AH_OFF + st_off + 16, sa_h + 8,  asz);
            CP16(sb + AH_OFF + st_off + 32, sa_h + 16, asz);
            CP16(sb + AH_OFF + st_off + 48, sa_h + 24, asz);
            CP16(sb + BH_OFF + st_off,      sb_h,      16u);
            CP16(sb + BH_OFF + st_off + 16, sb_h + 8,  16u);
            CP16(sb + BH_OFF + st_off + 32, sb_h + 16, 16u);
            CP16(sb + BH_OFF + st_off + 48, sb_h + 24, 16u);
        }
        CP_COMMIT();
    };

    issue(0);
    issue(1);

    for (int ch = 0; ch < nchunk; ch++) {
        CP_WAIT1();
        __syncthreads();
        issue(ch + 2);   // prefetch into buffer last read in iter ch-1

        uint32_t sb = sbase + (uint32_t)(ch % NSTG) * STG_B;
        #pragma unroll
        for (int ks = 0; ks < 4; ks++) {
            uint32_t kso = (uint32_t)(ks * 32);
            uint32_t ah[4][4], bh[4][2];
            #pragma unroll
            for (int mt = 0; mt < 4; mt++) {
                uint32_t ad = sb + a_lm + (uint32_t)(mt * 16 * ROWB) + kso;
                LDSM_X4(ah[mt][0], ah[mt][1], ah[mt][2], ah[mt][3], ad + AH_OFF);
            }
            #pragma unroll
            for (int nt2 = 0; nt2 < 2; nt2++) {
                uint32_t bd = sb + b_lm + (uint32_t)(nt2 * 16 * ROWB) + kso;
                uint32_t r0, r1, r2, r3;
                LDSM_X4(r0, r1, r2, r3, bd + BH_OFF);
                bh[2 * nt2][0] = r0; bh[2 * nt2][1] = r1;
                bh[2 * nt2 + 1][0] = r2; bh[2 * nt2 + 1][1] = r3;
            }
            #pragma unroll
            for (int mt = 0; mt < 4; mt++)
                #pragma unroll
                for (int nt = 0; nt < 4; nt++)
                    MMA16816F16(acc[mt][nt], ah[mt], bh[nt]);
        }
    }

    // fused SwiGLU epilogue via smem staging
    CP_WAIT0();
    __syncthreads();

    float* eps = (float*)dynsmem;
    int gr = lane >> 2, t4 = lane & 3;
    #pragma unroll
    for (int mt = 0; mt < 4; mt++) {
        int L0 = wm + mt * 16 + gr;
        int L1 = L0 + 8;
        #pragma unroll
        for (int nt = 0; nt < 4; nt++) {
            int C = wn + nt * 8 + t4 * 2;
            *(float2*)(eps + L0 * EP_LD + C) = make_float2(acc[mt][nt][0], acc[mt][nt][1]);
            *(float2*)(eps + L1 * EP_LD + C) = make_float2(acc[mt][nt][2], acc[mt][nt][3]);
        }
    }
    __syncthreads();

    {
        int r  = tid >> 1;
        int cb = (tid & 1) * 32;
        int R  = row0 + r;
        if (R < rend) {
            fp16* ho = Hout + (size_t)R * ldh + n0h + cb;
            #pragma unroll
            for (int i = 0; i < 8; i++) {
                float4 gv = *(float4*)(eps + r * EP_LD + cb + 4 * i);
                float4 uv = *(float4*)(eps + r * EP_LD + 64 + cb + 4 * i);
                float h0 = gv.x * uv.x / (1.f + expf(-gv.x));
                float h1 = gv.y * uv.y / (1.f + expf(-gv.y));
                float h2 = gv.z * uv.z / (1.f + expf(-gv.z));
                float h3 = gv.w * uv.w / (1.f + expf(-gv.w));
                __half2 p0 = __floats2half2_rn(h0, h1);
                __half2 p1 = __floats2half2_rn(h2, h3);
                *(uint2*)(ho + 4 * i) = make_uint2(*(uint32_t*)&p0, *(uint32_t*)&p1);
            }
        }
    }
}

// ======================= down_all: routed (z<NE) + shared (z==NE) ==============
__global__ void __launch_bounds__(256, 2)
down_all_kernel(const fp16* __restrict__ hh, const fp16* __restrict__ hsh,
                const fp16* __restrict__ dwh, const fp16* __restrict__ sdh,
                fp16* __restrict__ yh, float* __restrict__ ysh)
{
    int z = blockIdx.z;
    bool se = (z == NE);
    int rbeg, rend, lda, KD;
    const fp16 *Ah, *Bh;
    if (se) {
        rbeg = 0; rend = T_TOK; lda = 1024; KD = 1024;
        Ah = hsh; Bh = sdh;
    } else {
        rbeg = g_off[z]; rend = g_off[z + 1]; lda = 512; KD = 512;
        Ah = hh; Bh = dwh + (size_t)z * HDIM * IMOE;
    }
    int row0 = rbeg + blockIdx.y * 128;
    if (row0 >= rend) return;
    int n0 = blockIdx.x * 128;

    extern __shared__ __align__(16) char dynsmem[];
    uint32_t sbase = smem_u32(dynsmem);

    int tid  = threadIdx.x;
    int lane = tid & 31, wid = tid >> 5;
    int wm = (wid >> 2) * 64;
    int wn = (wid & 3) * 32;

    int srow = tid >> 1;
    int kh32 = (tid & 1) << 5;
    int  arow_s = row0 + srow;
    bool avalid = (arow_s < rend);
    const fp16* pAh = Ah;
    if (avalid) pAh = Ah + (size_t)arow_s * lda + kh32;
    const fp16* pBh = Bh + (size_t)(n0 + srow) * KD + kh32;
    uint32_t st_off = (uint32_t)(srow * ROWB + (tid & 1) * 64);
    uint32_t asz = avalid ? 16u : 0u;

    int a_r  = wm + (lane & 7) + ((lane >> 3) & 1) * 8;
    int a_k  = ((lane >> 4) & 1) * 8;
    uint32_t a_lm = (uint32_t)(a_r * ROWB + a_k * 2);
    int b_r  = wn + (lane & 7) + ((lane >> 4) & 1) * 8;
    int b_k  = ((lane >> 3) & 1) * 8;
    uint32_t b_lm = (uint32_t)(b_r * ROWB + b_k * 2);

    float acc[4][4][4];
    #pragma unroll
    for (int i = 0; i < 4; i++)
        #pragma unroll
        for (int j = 0; j < 4; j++)
            #pragma unroll
            for (int q = 0; q < 4; q++) acc[i][j][q] = 0.f;

    int nchunk = KD >> 6;   // 8 routed / 16 shared

    auto issue = [&](int ch) {
        if (ch < nchunk) {
            uint32_t sb = sbase + (uint32_t)(ch % NSTG) * STG_B;
            int k0 = ch << 6;
            const fp16* sa_h = pAh + k0;
            const fp16* sb_h = pBh + k0;
            CP16(sb + AH_OFF + st_off,      sa_h,      asz);
            CP16(sb + AH_OFF + st_off + 16, sa_h + 8,  asz);
            CP16(sb + AH_OFF + st_off + 32, sa_h + 16, asz);
            CP16(sb + AH_OFF + st_off + 48, sa_h + 24, asz);
            CP16(sb + BH_OFF + st_off,      sb_h,      16u);
            CP16(sb + BH_OFF + st_off + 16, sb_h + 8,  16u);
            CP16(sb + BH_OFF + st_off + 32, sb_h + 16, 16u);
            CP16(sb + BH_OFF + st_off + 48, sb_h + 24, 16u);
        }
        CP_COMMIT();
    };

    issue(0);
    issue(1);

    for (int ch = 0; ch < nchunk; ch++) {
        CP_WAIT1();
        __syncthreads();
        issue(ch + 2);

        uint32_t sb = sbase + (uint32_t)(ch % NSTG) * STG_B;
        #pragma unroll
        for (int ks = 0; ks < 4; ks++) {
            uint32_t kso = (uint32_t)(ks * 32);
            uint32_t ah[4][4], bh[4][2];
            #pragma unroll
            for (int mt = 0; mt < 4; mt++) {
                uint32_t ad = sb + a_lm + (uint32_t)(mt * 16 * ROWB) + kso;
                LDSM_X4(ah[mt][0], ah[mt][1], ah[mt][2], ah[mt][3], ad + AH_OFF);
            }
            #pragma unroll
            for (int nt2 = 0; nt2 < 2; nt2++) {
                uint32_t bd = sb + b_lm + (uint32_t)(nt2 * 16 * ROWB) + kso;
                uint32_t r0, r1, r2, r3;
                LDSM_X4(r0, r1, r2, r3, bd + BH_OFF);
                bh[2 * nt2][0] = r0; bh[2 * nt2][1] = r1;
                bh[2 * nt2 + 1][0] = r2; bh[2 * nt2 + 1][1] = r3;
            }
            #pragma unroll
            for (int mt = 0; mt < 4; mt++)
                #pragma unroll
                for (int nt = 0; nt < 4; nt++)
                    MMA16816F16(acc[mt][nt], ah[mt], bh[nt]);
        }
    }

    // epilogue
    int g = lane >> 2, t4 = lane & 3;
    #pragma unroll
    for (int mt = 0; mt < 4; mt++) {
        int R0 = row0 + wm + mt * 16 + g;
        int R1 = R0 + 8;
        bool v0 = (R0 < rend), v1 = (R1 < rend);
        #pragma unroll
        for (int nt = 0; nt < 4; nt++) {
            int C = n0 + wn + nt * 8 + t4 * 2;
            if (se) {
                if (v0) *(float2*)(ysh + (size_t)R0 * 1024 + C) =
                    make_float2(acc[mt][nt][0], acc[mt][nt][1]);
                if (v1) *(float2*)(ysh + (size_t)R1 * 1024 + C) =
                    make_float2(acc[mt][nt][2], acc[mt][nt][3]);
            } else {
                if (v0) {
                    float w0 = g_pw[R0];
                    __half2 p = __floats2half2_rn(acc[mt][nt][0] * w0, acc[mt][nt][1] * w0);
                    *(uint32_t*)(yh + (size_t)R0 * 1024 + C) = *(uint32_t*)&p;
                }
                if (v1) {
                    float w1 = g_pw[R1];
                    __half2 p = __floats2half2_rn(acc[mt][nt][2] * w1, acc[mt][nt][3] * w1);
                    *(uint32_t*)(yh + (size_t)R1 * 1024 + C) = *(uint32_t*)&p;
                }
            }
        }
    }
}

// ======================= combine ===============================================
__global__ void combine_kernel(float* __restrict__ out) {
    int idx = blockIdx.x * blockDim.x + threadIdx.x;
    int t = idx >> 8;
    int c = (idx & 255) << 2;
    float4 acc = *(const float4*)(g_ysh + (size_t)t * 1024 + c);
    #pragma unroll
    for (int r = 0; r < TOPK; r++) {
        int p = g_pos[t * TOPK + r];
        uint2 hv = *(const uint2*)(g_yh + (size_t)p * 1024 + c);
        __half2 a = *(__half2*)&hv.x;
        __half2 b = *(__half2*)&hv.y;
        float2 fa = __half22float2(a);
        float2 fb = __half22float2(b);
        acc.x += fa.x; acc.y += fa.y; acc.z += fb.x; acc.w += fb.y;
    }
    *(float4*)(out + (size_t)t * 1024 + c) = acc;
}

// ======================= launch ================================================
extern "C" void kernel_launch(void* const* d_in, const int* in_sizes, int n_in,
                              void* d_out, int out_size) {
    const float* x   = (const float*)d_in[0];
    const float* rw  = (const float*)d_in[1];
    const float* eb  = (const float*)d_in[2];
    const float* gw  = (const float*)d_in[3];
    const float* uw  = (const float*)d_in[4];
    const float* dw  = (const float*)d_in[5];
    const float* shg = (const float*)d_in[6];
    const float* shu = (const float*)d_in[7];
    const float* shd = (const float*)d_in[8];
    float* out = (float*)d_out;

    cudaFuncSetAttribute(gateup_all_kernel,
                         cudaFuncAttributeMaxDynamicSharedMemorySize, SMEM_DYN);
    cudaFuncSetAttribute(down_all_kernel,
                         cudaFuncAttributeMaxDynamicSharedMemorySize, SMEM_DYN);

    float *gys;
    fp16 *yh, *xh, *gwh, *uwh, *dwh, *sgh, *suh, *sdh, *hh, *hsh;
    cudaGetSymbolAddress((void**)&yh,   g_yh);
    cudaGetSymbolAddress((void**)&gys,  g_ysh);
    cudaGetSymbolAddress((void**)&xh,  g_xh);
    cudaGetSymbolAddress((void**)&gwh, g_gwh);
    cudaGetSymbolAddress((void**)&uwh, g_uwh);
    cudaGetSymbolAddress((void**)&dwh, g_dwh);
    cudaGetSymbolAddress((void**)&sgh, g_sgh);
    cudaGetSymbolAddress((void**)&suh, g_suh);
    cudaGetSymbolAddress((void**)&sdh, g_sdh);
    cudaGetSymbolAddress((void**)&hh,  g_hh);
    cudaGetSymbolAddress((void**)&hsh, g_hsh);

    // ---- fused convert + router ----
    CvtArgs ca;
    const float* srcs[NSEG] = {x, gw, uw, dw, shg, shu, shd};
    fp16*        dsts[NSEG] = {xh, gwh, uwh, dwh, sgh, suh, sdh};
    const int    n4s [NSEG] = {
        (T_TOK * HDIM) / 4,
        (NE * IMOE * HDIM) / 4, (NE * IMOE * HDIM) / 4, (NE * HDIM * IMOE) / 4,
        (HDIM * 1024) / 4, (HDIM * 1024) / 4, (HDIM * 1024) / 4
    };
    int cum = 0;
    for (int s = 0; s < NSEG; s++) {
        ca.src[s] = (const float4*)srcs[s];
        ca.dst[s] = (uint2*)dsts[s];
        ca.cum[s] = cum;
        cum += n4s[s];
    }
    prep_kernel<<<CVT_BLKS + T_TOK, 512>>>(ca, x, rw, eb);
    scan_kernel<<<1, 512>>>();
    scatter_kernel<<<(T_TOK * TOPK + 255) / 256, 256>>>();

    // ---- merged gate+up (+SwiGLU) for routed + shared ----
    gateup_all_kernel<<<dim3(16, 16, NE + 1), 256, SMEM_DYN>>>(
        xh, gwh, uwh, sgh, suh, hh, hsh);

    // ---- merged down for routed + shared ----
    down_all_kernel<<<dim3(8, 16, NE + 1), 256, SMEM_DYN>>>(
        hh, hsh, dwh, sdh, yh, gys);

    // ---- combine ----
    combine_kernel<<<(T_TOK * 1024 / 4) / 256, 256>>>(out);
}

// round 17
// speedup vs baseline: 1.1061x; 1.1061x over previous
#include <cuda_runtime.h>
#include <cuda_fp16.h>
#include <math.h>
#include <stdint.h>

#define T_TOK 2048
#define HDIM  1024
#define NE    16
#define TOPK  4
#define NG    4
#define TGSEL 2
#define IMOE  512
#define RSCALE 2.5f

typedef __half fp16;

// ======================= device scratch ========================================
__device__ int   g_tidx[T_TOK * TOPK];
__device__ float g_tw  [T_TOK * TOPK];
__device__ int   g_cur [NE];
__device__ int   g_off [NE + 1];
__device__ int   g_ptok[T_TOK * TOPK];
__device__ int   g_pos [T_TOK * TOPK];
__device__ float g_pw  [T_TOK * TOPK];

__device__ fp16  g_yh [(size_t)T_TOK * TOPK * 1024];   // routed down out (weighted, fp16)
__device__ float g_ysh[(size_t)T_TOK * 1024];           // shared down out (fp32)

// fp16 operands
__device__ fp16 g_xh [T_TOK * HDIM];
__device__ fp16 g_hh [T_TOK * TOPK * IMOE];
__device__ fp16 g_hsh[T_TOK * 1024];
__device__ fp16 g_gwh[NE * IMOE * HDIM];
__device__ fp16 g_uwh[NE * IMOE * HDIM];
__device__ fp16 g_dwh[NE * HDIM * IMOE];
__device__ fp16 g_sgh[HDIM * 1024];
__device__ fp16 g_suh[HDIM * 1024];
__device__ fp16 g_sdh[HDIM * 1024];

// ======================= fused prep: convert + router ==========================
#define NSEG 7
#define CVT_TOTAL 7602176            // total float4 units across all 7 segments
#define CVT_BLKS  (CVT_TOTAL / 512)  // 14848 (exact)

struct CvtArgs {
    const float4* src[NSEG];
    uint2*        dst[NSEG];
    int           cum[NSEG];
};

__global__ void __launch_bounds__(512)
prep_kernel(CvtArgs a,
            const float* __restrict__ x,
            const float* __restrict__ rw,
            const float* __restrict__ ebias) {
    if (blockIdx.x < CVT_BLKS) {
        int i = blockIdx.x * 512 + threadIdx.x;
        if (i < CVT_TOTAL) {
            int s = 0;
            #pragma unroll
            for (int k = 1; k < NSEG; k++) if (i >= a.cum[k]) s = k;
            int off = i - a.cum[s];
            float4 v = a.src[s][off];
            __half2 p0 = __floats2half2_rn(v.x, v.y);
            __half2 p1 = __floats2half2_rn(v.z, v.w);
            a.dst[s][off] = make_uint2(*(uint32_t*)&p0, *(uint32_t*)&p1);
        }
        return;
    }

    int t    = blockIdx.x - CVT_BLKS;
    int w    = threadIdx.x >> 5;
    int lane = threadIdx.x & 31;

    const float* xr = x  + (size_t)t * HDIM;
    const float* wr = rw + (size_t)w * HDIM;
    float s = 0.f;
    for (int k = lane; k < HDIM; k += 32) s += xr[k] * wr[k];
    #pragma unroll
    for (int o = 16; o; o >>= 1) s += __shfl_xor_sync(0xffffffffu, s, o);

    __shared__ float sdot[NE];
    if (lane == 0) sdot[w] = s;
    __syncthreads();

    if (threadIdx.x == 0) {
        float sraw[NE], sc[NE];
        #pragma unroll
        for (int e = 0; e < NE; e++) {
            sraw[e] = 1.f / (1.f + expf(-sdot[e]));
            sc[e]   = sraw[e] + ebias[e];
        }
        float gsc[NG];
        #pragma unroll
        for (int g = 0; g < NG; g++) {
            float m1 = -1e30f, m2 = -1e30f;
            #pragma unroll
            for (int j = 0; j < NE / NG; j++) {
                float v = sc[g * (NE / NG) + j];
                if (v > m1) { m2 = m1; m1 = v; }
                else if (v > m2) { m2 = v; }
            }
            gsc[g] = m1 + m2;
        }
        bool gsel[NG] = {false, false, false, false};
        for (int r = 0; r < TGSEL; r++) {
            int best = -1; float bv = -1e30f;
            for (int g = 0; g < NG; g++)
                if (!gsel[g] && gsc[g] > bv) { bv = gsc[g]; best = g; }
            gsel[best] = true;
        }
        float masked[NE];
        #pragma unroll
        for (int e = 0; e < NE; e++)
            masked[e] = gsel[e / (NE / NG)] ? sc[e] : 0.0f;
        int idx[TOPK]; float tw[TOPK]; float wsum = 0.f;
        for (int r = 0; r < TOPK; r++) {
            int best = 0; float bv = -1e30f;
            for (int e = 0; e < NE; e++)
                if (masked[e] > bv) { bv = masked[e]; best = e; }
            idx[r] = best; tw[r] = sraw[best];
            masked[best] = -1e30f;
            wsum += tw[r];
        }
        float inv = RSCALE / (wsum + 1e-20f);
        for (int r = 0; r < TOPK; r++) {
            g_tidx[t * TOPK + r] = idx[r];
            g_tw  [t * TOPK + r] = tw[r] * inv;
        }
    }
}

// ======================= scan (histogram + prefix) =============================
__global__ void __launch_bounds__(512)
scan_kernel() {
    __shared__ int cnt[NE];
    int tid = threadIdx.x;
    if (tid < NE) cnt[tid] = 0;
    __syncthreads();
    for (int i = tid; i < T_TOK * TOPK; i += 512)
        atomicAdd(&cnt[g_tidx[i]], 1);
    __syncthreads();
    if (tid == 0) {
        int acc = 0;
        for (int e = 0; e < NE; e++) { g_off[e] = acc; acc += cnt[e]; }
        g_off[NE] = acc;
    }
    if (tid < NE) g_cur[tid] = 0;
}

__global__ void scatter_kernel() {
    int s = blockIdx.x * blockDim.x + threadIdx.x;
    if (s >= T_TOK * TOPK) return;
    int e   = g_tidx[s];
    int pos = g_off[e] + atomicAdd(&g_cur[e], 1);
    g_ptok[pos] = s >> 2;
    g_pw  [pos] = g_tw[s];
    g_pos [s]   = pos;
}

// ======================= shared GEMM machinery =================================
// k-chunk 32, 80B padded rows, 4 stages (R14-proven config).
#define ROWB   80
#define AH_OFF 0
#define BH_OFF 10240
#define STG_B  20480
#define NSTG   4
#define SMEM_DYN (NSTG * STG_B)
#define EP_LD  132

static __device__ __forceinline__ uint32_t smem_u32(const void* p) {
    uint32_t a;
    asm("{ .reg .u64 t; cvta.to.shared.u64 t, %1; cvt.u32.u64 %0, t; }"
        : "=r"(a) : "l"(p));
    return a;
}

#define LDSM_X4(r0, r1, r2, r3, addr) \
    asm volatile("ldmatrix.sync.aligned.m8n8.x4.shared.b16 {%0,%1,%2,%3}, [%4];" \
        : "=r"(r0), "=r"(r1), "=r"(r2), "=r"(r3) : "r"(addr))

#define MMA16816F16(d, a, b) \
    asm volatile("mma.sync.aligned.m16n8k16.row.col.f32.f16.f16.f32 " \
        "{%0,%1,%2,%3},{%4,%5,%6,%7},{%8,%9},{%0,%1,%2,%3};" \
        : "+f"((d)[0]), "+f"((d)[1]), "+f"((d)[2]), "+f"((d)[3]) \
        : "r"((a)[0]), "r"((a)[1]), "r"((a)[2]), "r"((a)[3]), \
          "r"((b)[0]), "r"((b)[1]))

#define CP16(dst, src, sz) \
    asm volatile("cp.async.cg.shared.global [%0], [%1], 16, %2;" \
        :: "r"(dst), "l"(src), "r"(sz) : "memory")
#define CP_COMMIT() asm volatile("cp.async.commit_group;" ::: "memory")
#define CP_WAIT2()  asm volatile("cp.async.wait_group 2;" ::: "memory")
#define CP_WAIT0()  asm volatile("cp.async.wait_group 0;" ::: "memory")

// ======================= gateup_all: routed (z<NE) + shared (z==NE) ============
__global__ void __launch_bounds__(256, 2)
gateup_all_kernel(const fp16* __restrict__ xh,
                  const fp16* __restrict__ gwh, const fp16* __restrict__ uwh,
                  const fp16* __restrict__ sgh, const fp16* __restrict__ suh,
                  fp16* __restrict__ hh, fp16* __restrict__ hsh)
{
    int z = blockIdx.z;
    bool se = (z == NE);
    int rbeg, rend, nxb, ldh;
    const fp16 *Bg, *Bu;
    fp16* Hout;
    if (se) {
        rbeg = 0; rend = T_TOK; nxb = 16; ldh = 1024;
        Bg = sgh; Bu = suh; Hout = hsh;
    } else {
        rbeg = g_off[z]; rend = g_off[z + 1]; nxb = 8; ldh = 512;
        Bg = gwh + (size_t)z * IMOE * HDIM;
        Bu = uwh + (size_t)z * IMOE * HDIM;
        Hout = hh;
    }
    if (blockIdx.x >= nxb) return;
    int row0 = rbeg + blockIdx.y * 128;
    if (row0 >= rend) return;
    int n0h = blockIdx.x * 64;
    const int KD = 1024;

    extern __shared__ __align__(16) char dynsmem[];
    uint32_t sbase = smem_u32(dynsmem);

    int tid  = threadIdx.x;
    int lane = tid & 31, wid = tid >> 5;
    int wm = (wid >> 2) * 64;
    int wn = (wid & 3) * 32;

    int srow = tid >> 1;
    int kh16 = (tid & 1) << 4;
    int  arow_s = row0 + srow;
    bool avalid = (arow_s < rend);
    const fp16* pAh = xh;
    if (avalid) {
        int tokr = se ? arow_s : g_ptok[arow_s];
        pAh = xh + (size_t)tokr * HDIM + kh16;
    }
    const fp16* pBh = (srow < 64)
        ? Bg + (size_t)(n0h + srow) * KD + kh16
        : Bu + (size_t)(n0h + srow - 64) * KD + kh16;
    uint32_t st_off = (uint32_t)(srow * ROWB + (tid & 1) * 32);
    uint32_t asz = avalid ? 16u : 0u;

    int a_r  = wm + (lane & 7) + ((lane >> 3) & 1) * 8;
    int a_k  = ((lane >> 4) & 1) * 8;
    uint32_t a_lm = (uint32_t)(a_r * ROWB + a_k * 2);
    int b_r  = wn + (lane & 7) + ((lane >> 4) & 1) * 8;
    int b_k  = ((lane >> 3) & 1) * 8;
    uint32_t b_lm = (uint32_t)(b_r * ROWB + b_k * 2);

    float acc[4][4][4];
    #pragma unroll
    for (int i = 0; i < 4; i++)
        #pragma unroll
        for (int j = 0; j < 4; j++)
            #pragma unroll
            for (int q = 0; q < 4; q++) acc[i][j][q] = 0.f;

    const int nchunk = KD >> 5;   // 32

    auto issue = [&](int ch) {
        if (ch < nchunk) {
            uint32_t sb = sbase + (uint32_t)(ch % NSTG) * STG_B;
            int k0 = ch << 5;
            const fp16* sa_h = pAh + k0;
            const fp16* sb_h = pBh + k0;
            CP16(sb + AH_OFF + st_off,      sa_h,     asz);
            CP16(sb + AH_OFF + st_off + 16, sa_h + 8, asz);
            CP16(sb + BH_OFF + st_off,      sb_h,     16u);
            CP16(sb + BH_OFF + st_off + 16, sb_h + 8, 16u);
        }
        CP_COMMIT();
    };

    issue(0);
    issue(1);
    issue(2);

    for (int ch = 0; ch < nchunk; ch++) {
        CP_WAIT2();
        __syncthreads();
        // prefetch FIRST: overlap LDGSTS with this iteration's MMAs.
        // Buffer (ch+3)%4 was last read in iter ch-1 (ordered by the barrier).
        if (ch + 1 < nchunk) issue(ch + 3);

        uint32_t sb = sbase + (uint32_t)(ch % NSTG) * STG_B;
        #pragma unroll
        for (int ks = 0; ks < 2; ks++) {
            uint32_t kso = (uint32_t)(ks * 32);
            uint32_t ah[4][4], bh[4][2];
            #pragma unroll
            for (int mt = 0; mt < 4; mt++) {
                uint32_t ad = sb + a_lm + (uint32_t)(mt * 16 * ROWB) + kso;
                LDSM_X4(ah[mt][0], ah[mt][1], ah[mt][2], ah[mt][3], ad + AH_OFF);
            }
            #pragma unroll
            for (int nt2 = 0; nt2 < 2; nt2++) {
                uint32_t bd = sb + b_lm + (uint32_t)(nt2 * 16 * ROWB) + kso;
                uint32_t r0, r1, r2, r3;
                LDSM_X4(r0, r1, r2, r3, bd + BH_OFF);
                bh[2 * nt2][0] = r0; bh[2 * nt2][1] = r1;
                bh[2 * nt2 + 1][0] = r2; bh[2 * nt2 + 1][1] = r3;
            }
            #pragma unroll
            for (int mt = 0; mt < 4; mt++)
                #pragma unroll
                for (int nt = 0; nt < 4; nt++)
                    MMA16816F16(acc[mt][nt], ah[mt], bh[nt]);
        }
    }

    // fused SwiGLU epilogue via smem staging
    CP_WAIT0();
    __syncthreads();

    float* eps = (float*)dynsmem;
    int gr = lane >> 2, t4 = lane & 3;
    #pragma unroll
    for (int mt = 0; mt < 4; mt++) {
        int L0 = wm + mt * 16 + gr;
        int L1 = L0 + 8;
        #pragma unroll
        for (int nt = 0; nt < 4; nt++) {
            int C = wn + nt * 8 + t4 * 2;
            *(float2*)(eps + L0 * EP_LD + C) = make_float2(acc[mt][nt][0], acc[mt][nt][1]);
            *(float2*)(eps + L1 * EP_LD + C) = make_float2(acc[mt][nt][2], acc[mt][nt][3]);
        }
    }
    __syncthreads();

    {
        int r  = tid >> 1;
        int cb = (tid & 1) * 32;
        int R  = row0 + r;
        if (R < rend) {
            fp16* ho = Hout + (size_t)R * ldh + n0h + cb;
            #pragma unroll
            for (int i = 0; i < 8; i++) {
                float4 gv = *(float4*)(eps + r * EP_LD + cb + 4 * i);
                float4 uv = *(float4*)(eps + r * EP_LD + 64 + cb + 4 * i);
                float h0 = gv.x * uv.x / (1.f + expf(-gv.x));
                float h1 = gv.y * uv.y / (1.f + expf(-gv.y));
                float h2 = gv.z * uv.z / (1.f + expf(-gv.z));
                float h3 = gv.w * uv.w / (1.f + expf(-gv.w));
                __half2 p0 = __floats2half2_rn(h0, h1);
                __half2 p1 = __floats2half2_rn(h2, h3);
                *(uint2*)(ho + 4 * i) = make_uint2(*(uint32_t*)&p0, *(uint32_t*)&p1);
            }
        }
    }
}

// ======================= down_all: routed (z<NE) + shared (z==NE) ==============
__global__ void __launch_bounds__(256, 2)
down_all_kernel(const fp16* __restrict__ hh, const fp16* __restrict__ hsh,
                const fp16* __restrict__ dwh, const fp16* __restrict__ sdh,
                fp16* __restrict__ yh, float* __restrict__ ysh)
{
    int z = blockIdx.z;
    bool se = (z == NE);
    int rbeg, rend, lda, KD;
    const fp16 *Ah, *Bh;
    if (se) {
        rbeg = 0; rend = T_TOK; lda = 1024; KD = 1024;
        Ah = hsh; Bh = sdh;
    } else {
        rbeg = g_off[z]; rend = g_off[z + 1]; lda = 512; KD = 512;
        Ah = hh; Bh = dwh + (size_t)z * HDIM * IMOE;
    }
    int row0 = rbeg + blockIdx.y * 128;
    if (row0 >= rend) return;
    int n0 = blockIdx.x * 128;

    extern __shared__ __align__(16) char dynsmem[];
    uint32_t sbase = smem_u32(dynsmem);

    int tid  = threadIdx.x;
    int lane = tid & 31, wid = tid >> 5;
    int wm = (wid >> 2) * 64;
    int wn = (wid & 3) * 32;

    int srow = tid >> 1;
    int kh16 = (tid & 1) << 4;
    int  arow_s = row0 + srow;
    bool avalid = (arow_s < rend);
    const fp16* pAh = Ah;
    if (avalid) pAh = Ah + (size_t)arow_s * lda + kh16;
    const fp16* pBh = Bh + (size_t)(n0 + srow) * KD + kh16;
    uint32_t st_off = (uint32_t)(srow * ROWB + (tid & 1) * 32);
    uint32_t asz = avalid ? 16u : 0u;

    int a_r  = wm + (lane & 7) + ((lane >> 3) & 1) * 8;
    int a_k  = ((lane >> 4) & 1) * 8;
    uint32_t a_lm = (uint32_t)(a_r * ROWB + a_k * 2);
    int b_r  = wn + (lane & 7) + ((lane >> 4) & 1) * 8;
    int b_k  = ((lane >> 3) & 1) * 8;
    uint32_t b_lm = (uint32_t)(b_r * ROWB + b_k * 2);

    float acc[4][4][4];
    #pragma unroll
    for (int i = 0; i < 4; i++)
        #pragma unroll
        for (int j = 0; j < 4; j++)
            #pragma unroll
            for (int q = 0; q < 4; q++) acc[i][j][q] = 0.f;

    int nchunk = KD >> 5;

    auto issue = [&](int ch) {
        if (ch < nchunk) {
            uint32_t sb = sbase + (uint32_t)(ch % NSTG) * STG_B;
            int k0 = ch << 5;
            const fp16* sa_h = pAh + k0;
            const fp16* sb_h = pBh + k0;
            CP16(sb + AH_OFF + st_off,      sa_h,     asz);
            CP16(sb + AH_OFF + st_off + 16, sa_h + 8, asz);
            CP16(sb + BH_OFF + st_off,      sb_h,     16u);
            CP16(sb + BH_OFF + st_off + 16, sb_h + 8, 16u);
        }
        CP_COMMIT();
    };

    issue(0);
    issue(1);
    issue(2);

    for (int ch = 0; ch < nchunk; ch++) {
        CP_WAIT2();
        __syncthreads();
        if (ch + 1 < nchunk) issue(ch + 3);

        uint32_t sb = sbase + (uint32_t)(ch % NSTG) * STG_B;
        #pragma unroll
        for (int ks = 0; ks < 2; ks++) {
            uint32_t kso = (uint32_t)(ks * 32);
            uint32_t ah[4][4], bh[4][2];
            #pragma unroll
            for (int mt = 0; mt < 4; mt++) {
                uint32_t ad = sb + a_lm + (uint32_t)(mt * 16 * ROWB) + kso;
                LDSM_X4(ah[mt][0], ah[mt][1], ah[mt][2], ah[mt][3], ad + AH_OFF);
            }
            #pragma unroll
            for (int nt2 = 0; nt2 < 2; nt2++) {
                uint32_t bd = sb + b_lm + (uint32_t)(nt2 * 16 * ROWB) + kso;
                uint32_t r0, r1, r2, r3;
                LDSM_X4(r0, r1, r2, r3, bd + BH_OFF);
                bh[2 * nt2][0] = r0; bh[2 * nt2][1] = r1;
                bh[2 * nt2 + 1][0] = r2; bh[2 * nt2 + 1][1] = r3;
            }
            #pragma unroll
            for (int mt = 0; mt < 4; mt++)
                #pragma unroll
                for (int nt = 0; nt < 4; nt++)
                    MMA16816F16(acc[mt][nt], ah[mt], bh[nt]);
        }
    }

    // epilogue
    int g = lane >> 2, t4 = lane & 3;
    #pragma unroll
    for (int mt = 0; mt < 4; mt++) {
        int R0 = row0 + wm + mt * 16 + g;
        int R1 = R0 + 8;
        bool v0 = (R0 < rend), v1 = (R1 < rend);
        #pragma unroll
        for (int nt = 0; nt < 4; nt++) {
            int C = n0 + wn + nt * 8 + t4 * 2;
            if (se) {
                if (v0) *(float2*)(ysh + (size_t)R0 * 1024 + C) =
                    make_float2(acc[mt][nt][0], acc[mt][nt][1]);
                if (v1) *(float2*)(ysh + (size_t)R1 * 1024 + C) =
                    make_float2(acc[mt][nt][2], acc[mt][nt][3]);
            } else {
                if (v0) {
                    float w0 = g_pw[R0];
                    __half2 p = __floats2half2_rn(acc[mt][nt][0] * w0, acc[mt][nt][1] * w0);
                    *(uint32_t*)(yh + (size_t)R0 * 1024 + C) = *(uint32_t*)&p;
                }
                if (v1) {
                    float w1 = g_pw[R1];
                    __half2 p = __floats2half2_rn(acc[mt][nt][2] * w1, acc[mt][nt][3] * w1);
                    *(uint32_t*)(yh + (size_t)R1 * 1024 + C) = *(uint32_t*)&p;
                }
            }
        }
    }
}

// ======================= combine ===============================================
__global__ void combine_kernel(float* __restrict__ out) {
    int idx = blockIdx.x * blockDim.x + threadIdx.x;
    int t = idx >> 8;
    int c = (idx & 255) << 2;
    float4 acc = *(const float4*)(g_ysh + (size_t)t * 1024 + c);
    #pragma unroll
    for (int r = 0; r < TOPK; r++) {
        int p = g_pos[t * TOPK + r];
        uint2 hv = *(const uint2*)(g_yh + (size_t)p * 1024 + c);
        __half2 a = *(__half2*)&hv.x;
        __half2 b = *(__half2*)&hv.y;
        float2 fa = __half22float2(a);
        float2 fb = __half22float2(b);
        acc.x += fa.x; acc.y += fa.y; acc.z += fb.x; acc.w += fb.y;
    }
    *(float4*)(out + (size_t)t * 1024 + c) = acc;
}

// ======================= launch ================================================
extern "C" void kernel_launch(void* const* d_in, const int* in_sizes, int n_in,
                              void* d_out, int out_size) {
    const float* x   = (const float*)d_in[0];
    const float* rw  = (const float*)d_in[1];
    const float* eb  = (const float*)d_in[2];
    const float* gw  = (const float*)d_in[3];
    const float* uw  = (const float*)d_in[4];
    const float* dw  = (const float*)d_in[5];
    const float* shg = (const float*)d_in[6];
    const float* shu = (const float*)d_in[7];
    const float* shd = (const float*)d_in[8];
    float* out = (float*)d_out;

    cudaFuncSetAttribute(gateup_all_kernel,
                         cudaFuncAttributeMaxDynamicSharedMemorySize, SMEM_DYN);
    cudaFuncSetAttribute(down_all_kernel,
                         cudaFuncAttributeMaxDynamicSharedMemorySize, SMEM_DYN);

    float *gys;
    fp16 *yh, *xh, *gwh, *uwh, *dwh, *sgh, *suh, *sdh, *hh, *hsh;
    cudaGetSymbolAddress((void**)&yh,   g_yh);
    cudaGetSymbolAddress((void**)&gys,  g_ysh);
    cudaGetSymbolAddress((void**)&xh,  g_xh);
    cudaGetSymbolAddress((void**)&gwh, g_gwh);
    cudaGetSymbolAddress((void**)&uwh, g_uwh);
    cudaGetSymbolAddress((void**)&dwh, g_dwh);
    cudaGetSymbolAddress((void**)&sgh, g_sgh);
    cudaGetSymbolAddress((void**)&suh, g_suh);
    cudaGetSymbolAddress((void**)&sdh, g_sdh);
    cudaGetSymbolAddress((void**)&hh,  g_hh);
    cudaGetSymbolAddress((void**)&hsh, g_hsh);

    // ---- fused convert + router ----
    CvtArgs ca;
    const float* srcs[NSEG] = {x, gw, uw, dw, shg, shu, shd};
    fp16*        dsts[NSEG] = {xh, gwh, uwh, dwh, sgh, suh, sdh};
    const int    n4s [NSEG] = {
        (T_TOK * HDIM) / 4,
        (NE * IMOE * HDIM) / 4, (NE * IMOE * HDIM) / 4, (NE * HDIM * IMOE) / 4,
        (HDIM * 1024) / 4, (HDIM * 1024) / 4, (HDIM * 1024) / 4
    };
    int cum = 0;
    for (int s = 0; s < NSEG; s++) {
        ca.src[s] = (const float4*)srcs[s];
        ca.dst[s] = (uint2*)dsts[s];
        ca.cum[s] = cum;
        cum += n4s[s];
    }
    prep_kernel<<<CVT_BLKS + T_TOK, 512>>>(ca, x, rw, eb);
    scan_kernel<<<1, 512>>>();
    scatter_kernel<<<(T_TOK * TOPK + 255) / 256, 256>>>();

    // ---- merged gate+up (+SwiGLU) for routed + shared ----
    gateup_all_kernel<<<dim3(16, 16, NE + 1), 256, SMEM_DYN>>>(
        xh, gwh, uwh, sgh, suh, hh, hsh);

    // ---- merged down for routed + shared ----
    down_all_kernel<<<dim3(8, 16, NE + 1), 256, SMEM_DYN>>>(
        hh, hsh, dwh, sdh, yh, gys);

    // ---- combine ----
    combine_kernel<<<(T_TOK * 1024 / 4) / 256, 256>>>(out);
}